// round 12
// baseline (speedup 1.0000x reference)
#include <cuda_runtime.h>
#include <cuda_bf16.h>
#include <math_constants.h>
#include <cstdint>

#define NB      8192
#define ND      128
#define TM      128
#define MARGIN  1.0f
#define NT      (NB / TM)            // 64
#define NTRI    (NT * (NT + 1) / 2)  // 2080
#define NCLS    1024

// smem tile: 128 rows x 136 halves (272B padded rows -> conflict-free ldmatrix)
#define RSTRIDE 136
#define BUFB    (128 * RSTRIDE * 2)  // 34816 bytes per operand buffer

#define OFF_LI    0
#define OFF_LJ    512
#define OFF_SQI   1024
#define OFF_SQJ   1536
#define OFF_SCR_R 2048              // float [128][4]
#define OFF_SCR_C 4096              // float [128][2]
#define OFF_BUF   5120              // 2 x BUFB: A, B
#define SMEM_SZ   (OFF_BUF + 2 * BUFB)   // 74752 -> 2 CTAs/SM

#define PPCAP   131072               // ordered positive-pair capacity
#define PL_GRID 2048                 // pairloss blocks

// -------- scratch in device globals (no allocation allowed) --------
__device__ unsigned int g_hardest[NB];
__device__ float        g_sq[NB];
__device__ int          g_labels[NB];
__device__ float        g_total;
__device__ int          g_count;
__device__ int          g_done;
__device__ __nv_bfloat16 g_eb[NB * ND];          // bf16 embeddings
__device__ int          g_off[NCLS + 1];
__device__ unsigned long long g_pairs[PPCAP];    // packed (anchor<<32 | positive)
__device__ int          g_npair;

__device__ __forceinline__ uint32_t smem_u32(const void* p) {
    uint32_t a;
    asm("{ .reg .u64 t; cvta.to.shared.u64 t, %1; cvt.u32.u64 %0, t; }" : "=r"(a) : "l"(p));
    return a;
}
__device__ __forceinline__ void cp_async16(uint32_t dst, const void* src) {
    asm volatile("cp.async.cg.shared.global [%0], [%1], 16;" :: "r"(dst), "l"(src) : "memory");
}
__device__ __forceinline__ void cp_async_wait_all() {
    asm volatile("cp.async.commit_group;\n cp.async.wait_group 0;" ::: "memory");
}
__device__ __forceinline__ void ldm_x4(uint32_t* r, uint32_t addr) {
    asm volatile("ldmatrix.sync.aligned.m8n8.x4.shared.b16 {%0,%1,%2,%3}, [%4];"
                 : "=r"(r[0]), "=r"(r[1]), "=r"(r[2]), "=r"(r[3]) : "r"(addr));
}
__device__ __forceinline__ void mma_bf16(float* c, const uint32_t* a, uint32_t b0, uint32_t b1) {
    asm volatile(
        "mma.sync.aligned.m16n8k16.row.col.f32.bf16.bf16.f32 "
        "{%0,%1,%2,%3}, {%4,%5,%6,%7}, {%8,%9}, {%0,%1,%2,%3};"
        : "+f"(c[0]), "+f"(c[1]), "+f"(c[2]), "+f"(c[3])
        : "r"(a[0]), "r"(a[1]), "r"(a[2]), "r"(a[3]), "r"(b0), "r"(b1));
}
__device__ __forceinline__ int labels_are_64(const int* p) {
    int ok = 1;
    #pragma unroll
    for (int q = 0; q < 32; ++q) ok &= (p[2 * q + 1] == 0);
    return ok;
}

// ---------------- kernel 0: init (sq, labels, bf16 convert, hardest=inf) ----------------
__global__ void __launch_bounds__(256) init_kernel(const float* __restrict__ E,
                                                   const void* __restrict__ labels_raw) {
    int warp = (blockIdx.x * blockDim.x + threadIdx.x) >> 5;  // 0..2047
    int lane = threadIdx.x & 31;
    int row0 = warp * 4;

    float4 e[4];
    #pragma unroll
    for (int r = 0; r < 4; ++r)
        e[r] = __ldg((const float4*)(E + (size_t)(row0 + r) * ND + lane * 4));

    #pragma unroll
    for (int r = 0; r < 4; ++r) {
        float s = e[r].x * e[r].x + e[r].y * e[r].y + e[r].z * e[r].z + e[r].w * e[r].w;
        #pragma unroll
        for (int o = 16; o > 0; o >>= 1) s += __shfl_xor_sync(0xffffffffu, s, o);
        __nv_bfloat16 b0[4] = {__float2bfloat16(e[r].x), __float2bfloat16(e[r].y),
                               __float2bfloat16(e[r].z), __float2bfloat16(e[r].w)};
        *(ushort4*)(g_eb + (size_t)(row0 + r) * ND + lane * 4) = *(ushort4*)b0;
        if (lane == 0) {
            g_sq[row0 + r] = s;
            g_hardest[row0 + r] = 0x7f800000u;  // +inf
        }
    }
    if (lane < 4) {
        int i = row0 + lane;
        const int* p32 = (const int*)labels_raw;
        g_labels[i] = labels_are_64(p32) ? (int)((const long long*)labels_raw)[i] : p32[i];
    }
    if (blockIdx.x == 0 && threadIdx.x == 0) {
        g_total = 0.0f; g_count = 0; g_npair = 0; g_done = 0;
    }
}

// ---------------- kernel 0b: buckets + ordered positive-pair list (single block) ----------------
__global__ void __launch_bounds__(1024) bucket_kernel() {
    __shared__ int h[NCLS];
    __shared__ int sc[NCLS];
    __shared__ int cur[NCLS];
    __shared__ int members[NB];
    int t = threadIdx.x;
    h[t] = 0;
    __syncthreads();
    for (int i = t; i < NB; i += 1024) atomicAdd(&h[g_labels[i]], 1);
    __syncthreads();
    int v = h[t];
    sc[t] = v;
    __syncthreads();
    for (int off = 1; off < 1024; off <<= 1) {
        int x = (t >= off) ? sc[t - off] : 0;
        __syncthreads();
        sc[t] += x;
        __syncthreads();
    }
    int excl = sc[t] - v;
    g_off[t] = excl;
    cur[t] = excl;
    if (t == 0) g_off[NCLS] = NB;
    __syncthreads();
    for (int i = t; i < NB; i += 1024) {
        int pos = atomicAdd(&cur[g_labels[i]], 1);
        members[pos] = i;
    }
    __syncthreads();
    // ordered pairs: each anchor i emits (i, p) for all same-label p != i
    for (int i = t; i < NB; i += 1024) {
        int li = g_labels[i];
        int s = g_off[li], e = g_off[li + 1];
        int k = e - s - 1;
        if (k <= 0) continue;
        int base = atomicAdd(&g_npair, k);
        int w = 0;
        for (int idx = s; idx < e; ++idx) {
            int p = members[idx];
            if (p == i) continue;
            if (base + w < PPCAP)
                g_pairs[base + w] = ((unsigned long long)(unsigned)i << 32) | (unsigned)p;
            ++w;
        }
    }
}

// ---------------- kernel 1: triangular tile, bf16 HMMA + masked min (R8-proven epilogue) ----------------
extern __shared__ char smem_raw[];
__global__ void __launch_bounds__(256, 2) pass1_kernel() {
    // decode triangular block index b = it*(it+1)/2 + jt, jt <= it
    int b = blockIdx.x;
    int it = (int)((sqrtf(8.0f * (float)b + 1.0f) - 1.0f) * 0.5f);
    while ((it + 1) * (it + 2) / 2 <= b) ++it;
    while (it * (it + 1) / 2 > b) --it;
    int jt = b - it * (it + 1) / 2;
    const int diag = (it == jt);

    const int t    = threadIdx.x;
    const int wid  = t >> 5;
    const int lane = t & 31;
    const int wm   = wid >> 2;      // 0..1  (m half)
    const int wn   = wid & 3;       // 0..3  (n quarter)
    const int g    = lane >> 2;     // group
    const int qt   = lane & 3;      // thread in quad
    uint32_t sbase = smem_u32(smem_raw);

    // fill operand buffers with cp.async (skip B for diagonal tiles: A == B)
    const int nbuf = diag ? 1 : 2;
    for (int buf = 0; buf < nbuf; ++buf) {
        const char* src = (const char*)(g_eb + (size_t)((buf ? jt : it) * TM) * ND);
        uint32_t dst = sbase + OFF_BUF + buf * BUFB;
        #pragma unroll
        for (int q = 0; q < 8; ++q) {
            int idx = t + q * 256;           // 2048 chunks of 16B
            int row = idx >> 4, c16 = idx & 15;
            cp_async16(dst + row * (RSTRIDE * 2) + c16 * 16,
                       src + (size_t)row * 256 + c16 * 16);
        }
    }

    if (t < 128) {
        *(int*)  (smem_raw + OFF_LI  + t * 4) = g_labels[it * TM + t];
        *(float*)(smem_raw + OFF_SQI + t * 4) = g_sq[it * TM + t];
    } else {
        int c = t - 128;
        *(int*)  (smem_raw + OFF_LJ  + c * 4) = g_labels[jt * TM + c];
        *(float*)(smem_raw + OFF_SQJ + c * 4) = g_sq[jt * TM + c];
    }

    cp_async_wait_all();
    __syncthreads();

    // ldmatrix addressing (proven layout)
    uint32_t pA = sbase + OFF_BUF +
                  ((wm * 64 + (lane & 15)) * RSTRIDE + (lane >> 4) * 8) * 2;
    uint32_t pB = sbase + OFF_BUF + (diag ? 0 : BUFB) +
                  ((wn * 32 + ((lane >> 4) * 8) + (lane & 7)) * RSTRIDE +
                   ((lane >> 3) & 1) * 8) * 2;

    float acc[4][4][4];   // [mi][ni][c]
    #pragma unroll
    for (int mi = 0; mi < 4; ++mi)
        #pragma unroll
        for (int ni = 0; ni < 4; ++ni)
            #pragma unroll
            for (int c = 0; c < 4; ++c) acc[mi][ni][c] = 0.0f;

    #pragma unroll
    for (int ks = 0; ks < 8; ++ks) {
        uint32_t afr[4][4], bfr[2][4];
        #pragma unroll
        for (int mi = 0; mi < 4; ++mi)
            ldm_x4(afr[mi], pA + mi * (16 * RSTRIDE * 2) + ks * 32);
        #pragma unroll
        for (int np = 0; np < 2; ++np)
            ldm_x4(bfr[np], pB + np * (16 * RSTRIDE * 2) + ks * 32);
        #pragma unroll
        for (int mi = 0; mi < 4; ++mi)
            #pragma unroll
            for (int ni = 0; ni < 4; ++ni)
                mma_bf16(acc[mi][ni], afr[mi],
                         bfr[ni >> 1][(ni & 1) * 2], bfr[ni >> 1][(ni & 1) * 2 + 1]);
    }

    // ---------------- epilogue: masked row-min and col-min (scratch + combine) ----------------
    int   liR[4][2];  float sqiR[4][2];
    int   ljC[4][2];  float sqjC[4][2];
    #pragma unroll
    for (int mi = 0; mi < 4; ++mi)
        #pragma unroll
        for (int h = 0; h < 2; ++h) {
            int R = wm * 64 + mi * 16 + h * 8 + g;
            liR[mi][h]  = *(const int*)  (smem_raw + OFF_LI  + R * 4);
            sqiR[mi][h] = *(const float*)(smem_raw + OFF_SQI + R * 4);
        }
    #pragma unroll
    for (int ni = 0; ni < 4; ++ni)
        #pragma unroll
        for (int cb = 0; cb < 2; ++cb) {
            int C = wn * 32 + ni * 8 + qt * 2 + cb;
            ljC[ni][cb]  = *(const int*)  (smem_raw + OFF_LJ  + C * 4);
            sqjC[ni][cb] = *(const float*)(smem_raw + OFF_SQJ + C * 4);
        }

    float rowmin[4][2], colmin[4][2];
    #pragma unroll
    for (int x = 0; x < 4; ++x)
        #pragma unroll
        for (int y = 0; y < 2; ++y) { rowmin[x][y] = CUDART_INF_F; colmin[x][y] = CUDART_INF_F; }

    #pragma unroll
    for (int mi = 0; mi < 4; ++mi)
        #pragma unroll
        for (int ni = 0; ni < 4; ++ni)
            #pragma unroll
            for (int h = 0; h < 2; ++h)
                #pragma unroll
                for (int cb = 0; cb < 2; ++cb) {
                    float d = fmaf(-2.0f, acc[mi][ni][h * 2 + cb],
                                   sqiR[mi][h] + sqjC[ni][cb]);
                    float m = (ljC[ni][cb] != liR[mi][h]) ? d : CUDART_INF_F;
                    rowmin[mi][h]  = fminf(rowmin[mi][h], m);
                    colmin[ni][cb] = fminf(colmin[ni][cb], m);
                }

    #pragma unroll
    for (int mi = 0; mi < 4; ++mi)
        #pragma unroll
        for (int h = 0; h < 2; ++h) {
            float v = rowmin[mi][h];
            v = fminf(v, __shfl_xor_sync(0xffffffffu, v, 1));
            v = fminf(v, __shfl_xor_sync(0xffffffffu, v, 2));
            if (qt == 0) {
                int R = wm * 64 + mi * 16 + h * 8 + g;
                *(float*)(smem_raw + OFF_SCR_R + (R * 4 + wn) * 4) = v;
            }
        }
    #pragma unroll
    for (int ni = 0; ni < 4; ++ni)
        #pragma unroll
        for (int cb = 0; cb < 2; ++cb) {
            float v = colmin[ni][cb];
            v = fminf(v, __shfl_xor_sync(0xffffffffu, v, 4));
            v = fminf(v, __shfl_xor_sync(0xffffffffu, v, 8));
            v = fminf(v, __shfl_xor_sync(0xffffffffu, v, 16));
            if (lane < 4) {
                int C = wn * 32 + ni * 8 + qt * 2 + cb;
                *(float*)(smem_raw + OFF_SCR_C + (C * 2 + wm) * 4) = v;
            }
        }
    __syncthreads();

    if (t < 128) {
        const float* sr = (const float*)(smem_raw + OFF_SCR_R) + t * 4;
        float m = fminf(fminf(sr[0], sr[1]), fminf(sr[2], sr[3]));
        m = fmaxf(m, 0.0f);
        atomicMin(&g_hardest[it * TM + t], __float_as_uint(m));
    } else {
        int c = t - 128;
        const float* sc = (const float*)(smem_raw + OFF_SCR_C) + c * 2;
        float m = fminf(sc[0], sc[1]);
        m = fmaxf(m, 0.0f);
        atomicMin(&g_hardest[jt * TM + c], __float_as_uint(m));
    }
}

// ---------------- kernel 2: one warp per positive pair + last-block finalize ----------------
__global__ void __launch_bounds__(256) pairloss_kernel(const float* __restrict__ E,
                                                       float* out, int out_n) {
    int n = g_npair;
    if (n > PPCAP) n = PPCAP;
    int lane = threadIdx.x & 31;
    int warp = (blockIdx.x * blockDim.x + threadIdx.x) >> 5;
    int nwarps = (gridDim.x * blockDim.x) >> 5;

    float ls = 0.0f;
    int   lc = 0;
    for (int idx = warp; idx < n; idx += nwarps) {
        unsigned long long e = g_pairs[idx];
        int i = (int)(e >> 32);
        int p = (int)(unsigned)e;
        float4 a = __ldg((const float4*)(E + (size_t)i * ND + lane * 4));
        float4 f = __ldg((const float4*)(E + (size_t)p * ND + lane * 4));
        float pd = a.x * f.x + a.y * f.y + a.z * f.z + a.w * f.w;
        #pragma unroll
        for (int o = 16; o > 0; o >>= 1) pd += __shfl_xor_sync(0xffffffffu, pd, o);
        if (lane == 0) {
            float d  = fmaxf(g_sq[i] + g_sq[p] - 2.0f * pd, 0.0f);
            float hn = __uint_as_float(g_hardest[i]);   // +inf => no negative
            if (hn < d) {
                ls += fmaxf(d - hn + MARGIN, 0.0f);
                lc += 1;
            }
        }
    }
    if (lane == 0 && lc) {
        atomicAdd(&g_total, ls);
        atomicAdd(&g_count, lc);
    }

    // last-block finalization
    __syncthreads();
    __threadfence();
    __shared__ int is_last;
    if (threadIdx.x == 0)
        is_last = (atomicAdd(&g_done, 1) == (int)gridDim.x - 1);
    __syncthreads();
    if (is_last) {
        for (int i = threadIdx.x; i < out_n; i += blockDim.x) {
            if (i == 0) {
                int c = g_count;
                out[0] = g_total / (float)(c > 0 ? c : 1);
            } else if (i == 1) {
                out[1] = (float)g_count;
            } else {
                out[i] = 0.0f;
            }
        }
    }
}

extern "C" void kernel_launch(void* const* d_in, const int* in_sizes, int n_in,
                              void* d_out, int out_size) {
    const float* E   = (const float*)d_in[0];
    const void*  lab = d_in[1];

    cudaFuncSetAttribute(pass1_kernel, cudaFuncAttributeMaxDynamicSharedMemorySize, SMEM_SZ);

    init_kernel<<<NB / 32, 256>>>(E, lab);          // 256 blocks, 4 rows/warp
    bucket_kernel<<<1, 1024>>>();
    pass1_kernel<<<NTRI, 256, SMEM_SZ>>>();
    pairloss_kernel<<<PL_GRID, 256>>>(E, (float*)d_out, out_size);
}

// round 13
// speedup vs baseline: 1.1916x; 1.1916x over previous
#include <cuda_runtime.h>
#include <cuda_bf16.h>
#include <math_constants.h>
#include <cstdint>

#define NB      8192
#define ND      128
#define TM      128
#define MARGIN  1.0f
#define NT      (NB / TM)            // 64
#define NTRI    (NT * (NT + 1) / 2)  // 2080
#define NCLS    1024

// smem tile: 128 rows x 136 halves (272B padded rows -> conflict-free ldmatrix)
#define RSTRIDE 136
#define BUFB    (128 * RSTRIDE * 2)  // 34816 bytes per operand buffer

#define OFF_LI    0
#define OFF_LJ    512
#define OFF_SQI   1024
#define OFF_SQJ   1536
#define OFF_SCR_R 2048              // float [128][4]
#define OFF_SCR_C 4096              // float [128][2]
#define OFF_BUF   5120              // 2 x BUFB: A, B
#define SMEM_SZ   (OFF_BUF + 2 * BUFB)   // 74752 -> 2 CTAs/SM

#define PPCAP   131072               // ordered positive-pair capacity
#define PL_GRID 512                  // pairloss blocks

// -------- scratch in device globals (no allocation allowed) --------
__device__ unsigned int g_hardest[NB];
__device__ float        g_sq[NB];
__device__ int          g_labels[NB];
__device__ float        g_total;
__device__ int          g_count;
__device__ int          g_done;
__device__ __nv_bfloat16 g_eb[NB * ND];          // bf16 embeddings
__device__ int          g_off[NCLS + 1];
__device__ unsigned long long g_pairs[PPCAP];    // packed (anchor<<32 | positive)
__device__ int          g_npair;

__device__ __forceinline__ uint32_t smem_u32(const void* p) {
    uint32_t a;
    asm("{ .reg .u64 t; cvta.to.shared.u64 t, %1; cvt.u32.u64 %0, t; }" : "=r"(a) : "l"(p));
    return a;
}
__device__ __forceinline__ void cp_async16(uint32_t dst, const void* src) {
    asm volatile("cp.async.cg.shared.global [%0], [%1], 16;" :: "r"(dst), "l"(src) : "memory");
}
__device__ __forceinline__ void cp_async_wait_all() {
    asm volatile("cp.async.commit_group;\n cp.async.wait_group 0;" ::: "memory");
}
__device__ __forceinline__ void ldm_x4(uint32_t* r, uint32_t addr) {
    asm volatile("ldmatrix.sync.aligned.m8n8.x4.shared.b16 {%0,%1,%2,%3}, [%4];"
                 : "=r"(r[0]), "=r"(r[1]), "=r"(r[2]), "=r"(r[3]) : "r"(addr));
}
__device__ __forceinline__ void mma_bf16(float* c, const uint32_t* a, uint32_t b0, uint32_t b1) {
    asm volatile(
        "mma.sync.aligned.m16n8k16.row.col.f32.bf16.bf16.f32 "
        "{%0,%1,%2,%3}, {%4,%5,%6,%7}, {%8,%9}, {%0,%1,%2,%3};"
        : "+f"(c[0]), "+f"(c[1]), "+f"(c[2]), "+f"(c[3])
        : "r"(a[0]), "r"(a[1]), "r"(a[2]), "r"(a[3]), "r"(b0), "r"(b1));
}
__device__ __forceinline__ int labels_are_64(const int* p) {
    int ok = 1;
    #pragma unroll
    for (int q = 0; q < 32; ++q) ok &= (p[2 * q + 1] == 0);
    return ok;
}

// ---------------- kernel 0: init (sq, labels, bf16 convert, hardest=inf) ----------------
__global__ void __launch_bounds__(256) init_kernel(const float* __restrict__ E,
                                                   const void* __restrict__ labels_raw) {
    int warp = (blockIdx.x * blockDim.x + threadIdx.x) >> 5;  // 0..2047
    int lane = threadIdx.x & 31;
    int row0 = warp * 4;

    float4 e[4];
    #pragma unroll
    for (int r = 0; r < 4; ++r)
        e[r] = __ldg((const float4*)(E + (size_t)(row0 + r) * ND + lane * 4));

    #pragma unroll
    for (int r = 0; r < 4; ++r) {
        float s = e[r].x * e[r].x + e[r].y * e[r].y + e[r].z * e[r].z + e[r].w * e[r].w;
        #pragma unroll
        for (int o = 16; o > 0; o >>= 1) s += __shfl_xor_sync(0xffffffffu, s, o);
        __nv_bfloat16 b0[4] = {__float2bfloat16(e[r].x), __float2bfloat16(e[r].y),
                               __float2bfloat16(e[r].z), __float2bfloat16(e[r].w)};
        *(ushort4*)(g_eb + (size_t)(row0 + r) * ND + lane * 4) = *(ushort4*)b0;
        if (lane == 0) {
            g_sq[row0 + r] = s;
            g_hardest[row0 + r] = 0x7f800000u;  // +inf
        }
    }
    if (lane < 4) {
        int i = row0 + lane;
        const int* p32 = (const int*)labels_raw;
        g_labels[i] = labels_are_64(p32) ? (int)((const long long*)labels_raw)[i] : p32[i];
    }
    if (blockIdx.x == 0 && threadIdx.x == 0) {
        g_total = 0.0f; g_count = 0; g_done = 0;
    }
}

// ---------------- kernel 0b: buckets + ordered positive-pair list (single block) ----------------
__global__ void __launch_bounds__(1024) bucket_kernel() {
    __shared__ int h[NCLS];
    __shared__ int sc[NCLS];
    __shared__ int cur[NCLS];
    __shared__ int members[NB];
    __shared__ int npair_s;
    int t = threadIdx.x;
    h[t] = 0;
    if (t == 0) npair_s = 0;
    __syncthreads();
    for (int i = t; i < NB; i += 1024) atomicAdd(&h[g_labels[i]], 1);
    __syncthreads();
    int v = h[t];
    sc[t] = v;
    __syncthreads();
    for (int off = 1; off < 1024; off <<= 1) {
        int x = (t >= off) ? sc[t - off] : 0;
        __syncthreads();
        sc[t] += x;
        __syncthreads();
    }
    int excl = sc[t] - v;
    g_off[t] = excl;
    cur[t] = excl;
    if (t == 0) g_off[NCLS] = NB;
    __syncthreads();
    for (int i = t; i < NB; i += 1024) {
        int pos = atomicAdd(&cur[g_labels[i]], 1);
        members[pos] = i;
    }
    __syncthreads();
    // ordered pairs: anchor i emits (i, p) for all same-label p != i
    for (int i = t; i < NB; i += 1024) {
        int li = g_labels[i];
        int s = g_off[li], e = g_off[li + 1];
        int k = e - s - 1;
        if (k <= 0) continue;
        int base = atomicAdd(&npair_s, k);      // smem reservation
        int w = 0;
        for (int idx = s; idx < e; ++idx) {
            int p = members[idx];
            if (p == i) continue;
            if (base + w < PPCAP)
                g_pairs[base + w] = ((unsigned long long)(unsigned)i << 32) | (unsigned)p;
            ++w;
        }
    }
    __syncthreads();
    if (t == 0) g_npair = npair_s;
}

// ---------------- kernel 1: triangular tile, bf16 HMMA + masked min ----------------
extern __shared__ char smem_raw[];
__global__ void __launch_bounds__(256, 2) pass1_kernel() {
    // decode triangular block index b = it*(it+1)/2 + jt, jt <= it
    int b = blockIdx.x;
    int it = (int)((sqrtf(8.0f * (float)b + 1.0f) - 1.0f) * 0.5f);
    while ((it + 1) * (it + 2) / 2 <= b) ++it;
    while (it * (it + 1) / 2 > b) --it;
    int jt = b - it * (it + 1) / 2;
    const int diag = (it == jt);

    const int t    = threadIdx.x;
    const int wid  = t >> 5;
    const int lane = t & 31;
    const int wm   = wid >> 2;      // 0..1  (m half)
    const int wn   = wid & 3;       // 0..3  (n quarter)
    const int g    = lane >> 2;     // group
    const int qt   = lane & 3;      // thread in quad
    uint32_t sbase = smem_u32(smem_raw);

    // fill operand buffers with cp.async (skip B for diagonal tiles: A == B)
    const int nbuf = diag ? 1 : 2;
    for (int buf = 0; buf < nbuf; ++buf) {
        const char* src = (const char*)(g_eb + (size_t)((buf ? jt : it) * TM) * ND);
        uint32_t dst = sbase + OFF_BUF + buf * BUFB;
        #pragma unroll
        for (int q = 0; q < 8; ++q) {
            int idx = t + q * 256;           // 2048 chunks of 16B
            int row = idx >> 4, c16 = idx & 15;
            cp_async16(dst + row * (RSTRIDE * 2) + c16 * 16,
                       src + (size_t)row * 256 + c16 * 16);
        }
    }

    if (t < 128) {
        *(int*)  (smem_raw + OFF_LI  + t * 4) = g_labels[it * TM + t];
        *(float*)(smem_raw + OFF_SQI + t * 4) = g_sq[it * TM + t];
    } else {
        int c = t - 128;
        *(int*)  (smem_raw + OFF_LJ  + c * 4) = g_labels[jt * TM + c];
        *(float*)(smem_raw + OFF_SQJ + c * 4) = g_sq[jt * TM + c];
    }

    cp_async_wait_all();
    __syncthreads();

    // ldmatrix addressing (proven layout)
    uint32_t pA = sbase + OFF_BUF +
                  ((wm * 64 + (lane & 15)) * RSTRIDE + (lane >> 4) * 8) * 2;
    uint32_t pB = sbase + OFF_BUF + (diag ? 0 : BUFB) +
                  ((wn * 32 + ((lane >> 4) * 8) + (lane & 7)) * RSTRIDE +
                   ((lane >> 3) & 1) * 8) * 2;

    float acc[4][4][4];   // [mi][ni][c]
    #pragma unroll
    for (int mi = 0; mi < 4; ++mi)
        #pragma unroll
        for (int ni = 0; ni < 4; ++ni)
            #pragma unroll
            for (int c = 0; c < 4; ++c) acc[mi][ni][c] = 0.0f;

    #pragma unroll
    for (int ks = 0; ks < 8; ++ks) {
        uint32_t afr[4][4], bfr[2][4];
        #pragma unroll
        for (int mi = 0; mi < 4; ++mi)
            ldm_x4(afr[mi], pA + mi * (16 * RSTRIDE * 2) + ks * 32);
        #pragma unroll
        for (int np = 0; np < 2; ++np)
            ldm_x4(bfr[np], pB + np * (16 * RSTRIDE * 2) + ks * 32);
        #pragma unroll
        for (int mi = 0; mi < 4; ++mi)
            #pragma unroll
            for (int ni = 0; ni < 4; ++ni)
                mma_bf16(acc[mi][ni], afr[mi],
                         bfr[ni >> 1][(ni & 1) * 2], bfr[ni >> 1][(ni & 1) * 2 + 1]);
    }

    // ---------------- epilogue: masked row-min and col-min (scratch + combine) ----------------
    int   liR[4][2];  float sqiR[4][2];
    int   ljC[4][2];  float sqjC[4][2];
    #pragma unroll
    for (int mi = 0; mi < 4; ++mi)
        #pragma unroll
        for (int h = 0; h < 2; ++h) {
            int R = wm * 64 + mi * 16 + h * 8 + g;
            liR[mi][h]  = *(const int*)  (smem_raw + OFF_LI  + R * 4);
            sqiR[mi][h] = *(const float*)(smem_raw + OFF_SQI + R * 4);
        }
    #pragma unroll
    for (int ni = 0; ni < 4; ++ni)
        #pragma unroll
        for (int cb = 0; cb < 2; ++cb) {
            int C = wn * 32 + ni * 8 + qt * 2 + cb;
            ljC[ni][cb]  = *(const int*)  (smem_raw + OFF_LJ  + C * 4);
            sqjC[ni][cb] = *(const float*)(smem_raw + OFF_SQJ + C * 4);
        }

    float rowmin[4][2], colmin[4][2];
    #pragma unroll
    for (int x = 0; x < 4; ++x)
        #pragma unroll
        for (int y = 0; y < 2; ++y) { rowmin[x][y] = CUDART_INF_F; colmin[x][y] = CUDART_INF_F; }

    #pragma unroll
    for (int mi = 0; mi < 4; ++mi)
        #pragma unroll
        for (int ni = 0; ni < 4; ++ni)
            #pragma unroll
            for (int h = 0; h < 2; ++h)
                #pragma unroll
                for (int cb = 0; cb < 2; ++cb) {
                    float d = fmaf(-2.0f, acc[mi][ni][h * 2 + cb],
                                   sqiR[mi][h] + sqjC[ni][cb]);
                    float m = (ljC[ni][cb] != liR[mi][h]) ? d : CUDART_INF_F;
                    rowmin[mi][h]  = fminf(rowmin[mi][h], m);
                    colmin[ni][cb] = fminf(colmin[ni][cb], m);
                }

    #pragma unroll
    for (int mi = 0; mi < 4; ++mi)
        #pragma unroll
        for (int h = 0; h < 2; ++h) {
            float v = rowmin[mi][h];
            v = fminf(v, __shfl_xor_sync(0xffffffffu, v, 1));
            v = fminf(v, __shfl_xor_sync(0xffffffffu, v, 2));
            if (qt == 0) {
                int R = wm * 64 + mi * 16 + h * 8 + g;
                *(float*)(smem_raw + OFF_SCR_R + (R * 4 + wn) * 4) = v;
            }
        }
    #pragma unroll
    for (int ni = 0; ni < 4; ++ni)
        #pragma unroll
        for (int cb = 0; cb < 2; ++cb) {
            float v = colmin[ni][cb];
            v = fminf(v, __shfl_xor_sync(0xffffffffu, v, 4));
            v = fminf(v, __shfl_xor_sync(0xffffffffu, v, 8));
            v = fminf(v, __shfl_xor_sync(0xffffffffu, v, 16));
            if (lane < 4) {
                int C = wn * 32 + ni * 8 + qt * 2 + cb;
                *(float*)(smem_raw + OFF_SCR_C + (C * 2 + wm) * 4) = v;
            }
        }
    __syncthreads();

    if (t < 128) {
        const float* sr = (const float*)(smem_raw + OFF_SCR_R) + t * 4;
        float m = fminf(fminf(sr[0], sr[1]), fminf(sr[2], sr[3]));
        m = fmaxf(m, 0.0f);
        atomicMin(&g_hardest[it * TM + t], __float_as_uint(m));
    } else {
        int c = t - 128;
        const float* sc = (const float*)(smem_raw + OFF_SCR_C) + c * 2;
        float m = fminf(sc[0], sc[1]);
        m = fmaxf(m, 0.0f);
        atomicMin(&g_hardest[jt * TM + c], __float_as_uint(m));
    }
}

// ---------------- kernel 2: one warp per pair, block-reduced accumulation ----------------
__global__ void __launch_bounds__(256) pairloss_kernel(const float* __restrict__ E,
                                                       float* out, int out_n) {
    __shared__ float s_ls[8];
    __shared__ int   s_lc[8];
    int n = g_npair;
    if (n > PPCAP) n = PPCAP;
    int lane  = threadIdx.x & 31;
    int warpl = threadIdx.x >> 5;      // warp within block (0..7)
    int warp  = (blockIdx.x * blockDim.x + threadIdx.x) >> 5;
    int nwarps = (gridDim.x * blockDim.x) >> 5;

    float ls = 0.0f;
    int   lc = 0;
    for (int idx = warp; idx < n; idx += nwarps) {
        unsigned long long e = g_pairs[idx];
        int i = (int)(e >> 32);
        int p = (int)(unsigned)e;
        float4 a = __ldg((const float4*)(E + (size_t)i * ND + lane * 4));
        float4 f = __ldg((const float4*)(E + (size_t)p * ND + lane * 4));
        float pd = a.x * f.x + a.y * f.y + a.z * f.z + a.w * f.w;
        #pragma unroll
        for (int o = 16; o > 0; o >>= 1) pd += __shfl_xor_sync(0xffffffffu, pd, o);
        if (lane == 0) {
            float d  = fmaxf(g_sq[i] + g_sq[p] - 2.0f * pd, 0.0f);
            float hn = __uint_as_float(g_hardest[i]);   // +inf => no negative
            if (hn < d) {
                ls += fmaxf(d - hn + MARGIN, 0.0f);
                lc += 1;
            }
        }
    }
    // block-level reduction: ONE atomic pair per block
    if (lane == 0) { s_ls[warpl] = ls; s_lc[warpl] = lc; }
    __syncthreads();
    if (threadIdx.x == 0) {
        float bls = 0.0f;
        int   blc = 0;
        #pragma unroll
        for (int w = 0; w < 8; ++w) { bls += s_ls[w]; blc += s_lc[w]; }
        if (blc) {
            atomicAdd(&g_total, bls);
            atomicAdd(&g_count, blc);
        }
    }

    // last-block finalization
    __syncthreads();
    __threadfence();
    __shared__ int is_last;
    if (threadIdx.x == 0)
        is_last = (atomicAdd(&g_done, 1) == (int)gridDim.x - 1);
    __syncthreads();
    if (is_last) {
        for (int i = threadIdx.x; i < out_n; i += blockDim.x) {
            if (i == 0) {
                int c = g_count;
                out[0] = g_total / (float)(c > 0 ? c : 1);
            } else if (i == 1) {
                out[1] = (float)g_count;
            } else {
                out[i] = 0.0f;
            }
        }
    }
}

extern "C" void kernel_launch(void* const* d_in, const int* in_sizes, int n_in,
                              void* d_out, int out_size) {
    const float* E   = (const float*)d_in[0];
    const void*  lab = d_in[1];

    cudaFuncSetAttribute(pass1_kernel, cudaFuncAttributeMaxDynamicSharedMemorySize, SMEM_SZ);

    init_kernel<<<NB / 32, 256>>>(E, lab);          // 256 blocks, 4 rows/warp
    bucket_kernel<<<1, 1024>>>();
    pass1_kernel<<<NTRI, 256, SMEM_SZ>>>();
    pairloss_kernel<<<PL_GRID, 256>>>(E, (float*)d_out, out_size);
}

// round 14
// speedup vs baseline: 1.8315x; 1.5370x over previous
#include <cuda_runtime.h>
#include <cuda_bf16.h>
#include <math_constants.h>
#include <cstdint>

#define NB      8192
#define ND      128
#define TM      128
#define MARGIN  1.0f
#define NT      (NB / TM)            // 64
#define NTRI    (NT * (NT + 1) / 2)  // 2080

// smem tile: 128 rows x 136 halves (272B padded rows -> conflict-free ldmatrix)
#define RSTRIDE 136
#define BUFB    (128 * RSTRIDE * 2)  // 34816 bytes per operand buffer

#define OFF_LI    0
#define OFF_LJ    512
#define OFF_SQI   1024
#define OFF_SQJ   1536
#define OFF_SCR_R 2048              // float [128][4]
#define OFF_SCR_C 4096              // float [128][2]
#define OFF_BUF   5120              // 2 x BUFB: A, B
#define SMEM_SZ   (OFF_BUF + 2 * BUFB)   // 74752 -> 2 CTAs/SM

#define PPCAP   131072               // positive-pair entry capacity
#define PL_GRID 296                  // pairloss blocks (2 per SM)

// -------- scratch in device globals (no allocation allowed) --------
__device__ unsigned int g_hardest[NB];
__device__ float        g_sq[NB];
__device__ int          g_labels[NB];
__device__ float        g_total;
__device__ int          g_count;
__device__ int          g_done;
__device__ __nv_bfloat16 g_eb[NB * ND];          // bf16 embeddings
__device__ unsigned long long g_pp[PPCAP];       // packed (anchor<<32 | f32bits(d_pos))
__device__ int          g_pp_n;

__device__ __forceinline__ uint32_t smem_u32(const void* p) {
    uint32_t a;
    asm("{ .reg .u64 t; cvta.to.shared.u64 t, %1; cvt.u32.u64 %0, t; }" : "=r"(a) : "l"(p));
    return a;
}
__device__ __forceinline__ void cp_async16(uint32_t dst, const void* src) {
    asm volatile("cp.async.cg.shared.global [%0], [%1], 16;" :: "r"(dst), "l"(src) : "memory");
}
__device__ __forceinline__ void cp_async_wait_all() {
    asm volatile("cp.async.commit_group;\n cp.async.wait_group 0;" ::: "memory");
}
__device__ __forceinline__ void ldm_x4(uint32_t* r, uint32_t addr) {
    asm volatile("ldmatrix.sync.aligned.m8n8.x4.shared.b16 {%0,%1,%2,%3}, [%4];"
                 : "=r"(r[0]), "=r"(r[1]), "=r"(r[2]), "=r"(r[3]) : "r"(addr));
}
__device__ __forceinline__ void mma_bf16(float* c, const uint32_t* a, uint32_t b0, uint32_t b1) {
    asm volatile(
        "mma.sync.aligned.m16n8k16.row.col.f32.bf16.bf16.f32 "
        "{%0,%1,%2,%3}, {%4,%5,%6,%7}, {%8,%9}, {%0,%1,%2,%3};"
        : "+f"(c[0]), "+f"(c[1]), "+f"(c[2]), "+f"(c[3])
        : "r"(a[0]), "r"(a[1]), "r"(a[2]), "r"(a[3]), "r"(b0), "r"(b1));
}
__device__ __forceinline__ int labels_are_64(const int* p) {
    int ok = 1;
    #pragma unroll
    for (int q = 0; q < 32; ++q) ok &= (p[2 * q + 1] == 0);
    return ok;
}

// ---------------- kernel 0: init (sq, labels, bf16 convert, hardest=inf) ----------------
__global__ void __launch_bounds__(256) init_kernel(const float* __restrict__ E,
                                                   const void* __restrict__ labels_raw) {
    int warp = (blockIdx.x * blockDim.x + threadIdx.x) >> 5;  // 0..2047
    int lane = threadIdx.x & 31;
    int row0 = warp * 4;

    float4 e[4];
    #pragma unroll
    for (int r = 0; r < 4; ++r)
        e[r] = __ldg((const float4*)(E + (size_t)(row0 + r) * ND + lane * 4));

    #pragma unroll
    for (int r = 0; r < 4; ++r) {
        float s = e[r].x * e[r].x + e[r].y * e[r].y + e[r].z * e[r].z + e[r].w * e[r].w;
        #pragma unroll
        for (int o = 16; o > 0; o >>= 1) s += __shfl_xor_sync(0xffffffffu, s, o);
        __nv_bfloat16 b0[4] = {__float2bfloat16(e[r].x), __float2bfloat16(e[r].y),
                               __float2bfloat16(e[r].z), __float2bfloat16(e[r].w)};
        *(ushort4*)(g_eb + (size_t)(row0 + r) * ND + lane * 4) = *(ushort4*)b0;
        if (lane == 0) {
            g_sq[row0 + r] = s;
            g_hardest[row0 + r] = 0x7f800000u;  // +inf
        }
    }
    if (lane < 4) {
        int i = row0 + lane;
        const int* p32 = (const int*)labels_raw;
        g_labels[i] = labels_are_64(p32) ? (int)((const long long*)labels_raw)[i] : p32[i];
    }
    if (blockIdx.x == 0 && threadIdx.x == 0) {
        g_total = 0.0f; g_count = 0; g_pp_n = 0; g_done = 0;
    }
}

// ---------------- kernel 1: triangular tile, bf16 HMMA + masked min + slim harvest ----------------
extern __shared__ char smem_raw[];
__global__ void __launch_bounds__(256, 2) pass1_kernel() {
    // decode triangular block index b = it*(it+1)/2 + jt, jt <= it
    int b = blockIdx.x;
    int it = (int)((sqrtf(8.0f * (float)b + 1.0f) - 1.0f) * 0.5f);
    while ((it + 1) * (it + 2) / 2 <= b) ++it;
    while (it * (it + 1) / 2 > b) --it;
    int jt = b - it * (it + 1) / 2;
    const int diag = (it == jt);

    const int t    = threadIdx.x;
    const int wid  = t >> 5;
    const int lane = t & 31;
    const int wm   = wid >> 2;      // 0..1  (m half)
    const int wn   = wid & 3;       // 0..3  (n quarter)
    const int g    = lane >> 2;     // group
    const int qt   = lane & 3;      // thread in quad
    uint32_t sbase = smem_u32(smem_raw);

    // fill operand buffers with cp.async (skip B for diagonal tiles: A == B)
    const int nbuf = diag ? 1 : 2;
    for (int buf = 0; buf < nbuf; ++buf) {
        const char* src = (const char*)(g_eb + (size_t)((buf ? jt : it) * TM) * ND);
        uint32_t dst = sbase + OFF_BUF + buf * BUFB;
        #pragma unroll
        for (int q = 0; q < 8; ++q) {
            int idx = t + q * 256;           // 2048 chunks of 16B
            int row = idx >> 4, c16 = idx & 15;
            cp_async16(dst + row * (RSTRIDE * 2) + c16 * 16,
                       src + (size_t)row * 256 + c16 * 16);
        }
    }

    if (t < 128) {
        *(int*)  (smem_raw + OFF_LI  + t * 4) = g_labels[it * TM + t];
        *(float*)(smem_raw + OFF_SQI + t * 4) = g_sq[it * TM + t];
    } else {
        int c = t - 128;
        *(int*)  (smem_raw + OFF_LJ  + c * 4) = g_labels[jt * TM + c];
        *(float*)(smem_raw + OFF_SQJ + c * 4) = g_sq[jt * TM + c];
    }

    cp_async_wait_all();
    __syncthreads();

    // ldmatrix addressing (proven layout)
    uint32_t pA = sbase + OFF_BUF +
                  ((wm * 64 + (lane & 15)) * RSTRIDE + (lane >> 4) * 8) * 2;
    uint32_t pB = sbase + OFF_BUF + (diag ? 0 : BUFB) +
                  ((wn * 32 + ((lane >> 4) * 8) + (lane & 7)) * RSTRIDE +
                   ((lane >> 3) & 1) * 8) * 2;

    float acc[4][4][4];   // [mi][ni][c]
    #pragma unroll
    for (int mi = 0; mi < 4; ++mi)
        #pragma unroll
        for (int ni = 0; ni < 4; ++ni)
            #pragma unroll
            for (int c = 0; c < 4; ++c) acc[mi][ni][c] = 0.0f;

    #pragma unroll
    for (int ks = 0; ks < 8; ++ks) {
        uint32_t afr[4][4], bfr[2][4];
        #pragma unroll
        for (int mi = 0; mi < 4; ++mi)
            ldm_x4(afr[mi], pA + mi * (16 * RSTRIDE * 2) + ks * 32);
        #pragma unroll
        for (int np = 0; np < 2; ++np)
            ldm_x4(bfr[np], pB + np * (16 * RSTRIDE * 2) + ks * 32);
        #pragma unroll
        for (int mi = 0; mi < 4; ++mi)
            #pragma unroll
            for (int ni = 0; ni < 4; ++ni)
                mma_bf16(acc[mi][ni], afr[mi],
                         bfr[ni >> 1][(ni & 1) * 2], bfr[ni >> 1][(ni & 1) * 2 + 1]);
    }

    // ---------------- epilogue: masked min (scratch+combine) + slim harvest ----------------
    int   rL[4][2], cL[4][2];        // local tile indices
    int   RG[4][2], CG[4][2];        // global ids (precomputed once -> slim emit sites)
    int   liR[4][2], ljC[4][2];
    float sqiR[4][2], sqjC[4][2];
    #pragma unroll
    for (int mi = 0; mi < 4; ++mi)
        #pragma unroll
        for (int h = 0; h < 2; ++h) {
            int r = wm * 64 + mi * 16 + h * 8 + g;
            rL[mi][h]   = r;
            RG[mi][h]   = it * TM + r;
            liR[mi][h]  = *(const int*)  (smem_raw + OFF_LI  + r * 4);
            sqiR[mi][h] = *(const float*)(smem_raw + OFF_SQI + r * 4);
        }
    #pragma unroll
    for (int ni = 0; ni < 4; ++ni)
        #pragma unroll
        for (int cb = 0; cb < 2; ++cb) {
            int c = wn * 32 + ni * 8 + qt * 2 + cb;
            cL[ni][cb]   = c;
            CG[ni][cb]   = jt * TM + c;
            ljC[ni][cb]  = *(const int*)  (smem_raw + OFF_LJ  + c * 4);
            sqjC[ni][cb] = *(const float*)(smem_raw + OFF_SQJ + c * 4);
        }

    const bool nondiag = !diag;
    float rowmin[4][2], colmin[4][2];
    #pragma unroll
    for (int x = 0; x < 4; ++x)
        #pragma unroll
        for (int y = 0; y < 2; ++y) { rowmin[x][y] = CUDART_INF_F; colmin[x][y] = CUDART_INF_F; }

    #pragma unroll
    for (int mi = 0; mi < 4; ++mi)
        #pragma unroll
        for (int ni = 0; ni < 4; ++ni)
            #pragma unroll
            for (int h = 0; h < 2; ++h)
                #pragma unroll
                for (int cb = 0; cb < 2; ++cb) {
                    float d = fmaf(-2.0f, acc[mi][ni][h * 2 + cb],
                                   sqiR[mi][h] + sqjC[ni][cb]);
                    if (ljC[ni][cb] != liR[mi][h]) {
                        rowmin[mi][h]  = fminf(rowmin[mi][h], d);
                        colmin[ni][cb] = fminf(colmin[ni][cb], d);
                    } else if (nondiag || RG[mi][h] > CG[ni][cb]) {
                        // positive pair: emit for both orientations (rare)
                        unsigned db = __float_as_uint(fmaxf(d, 0.0f));
                        int pos = atomicAdd(&g_pp_n, 2);
                        if (pos <= PPCAP - 2) {
                            g_pp[pos]     = ((unsigned long long)(unsigned)RG[mi][h] << 32) | db;
                            g_pp[pos + 1] = ((unsigned long long)(unsigned)CG[ni][cb] << 32) | db;
                        }
                    }
                }

    // proven scratch + combine epilogue (deduplicates before L2 atomics)
    #pragma unroll
    for (int mi = 0; mi < 4; ++mi)
        #pragma unroll
        for (int h = 0; h < 2; ++h) {
            float v = rowmin[mi][h];
            v = fminf(v, __shfl_xor_sync(0xffffffffu, v, 1));
            v = fminf(v, __shfl_xor_sync(0xffffffffu, v, 2));
            if (qt == 0)
                *(float*)(smem_raw + OFF_SCR_R + (rL[mi][h] * 4 + wn) * 4) = v;
        }
    #pragma unroll
    for (int ni = 0; ni < 4; ++ni)
        #pragma unroll
        for (int cb = 0; cb < 2; ++cb) {
            float v = colmin[ni][cb];
            v = fminf(v, __shfl_xor_sync(0xffffffffu, v, 4));
            v = fminf(v, __shfl_xor_sync(0xffffffffu, v, 8));
            v = fminf(v, __shfl_xor_sync(0xffffffffu, v, 16));
            if (lane < 4)
                *(float*)(smem_raw + OFF_SCR_C + (cL[ni][cb] * 2 + wm) * 4) = v;
        }
    __syncthreads();

    if (t < 128) {
        const float* sr = (const float*)(smem_raw + OFF_SCR_R) + t * 4;
        float m = fminf(fminf(sr[0], sr[1]), fminf(sr[2], sr[3]));
        m = fmaxf(m, 0.0f);
        atomicMin(&g_hardest[it * TM + t], __float_as_uint(m));
    } else {
        int c = t - 128;
        const float* sc = (const float*)(smem_raw + OFF_SCR_C) + c * 2;
        float m = fminf(sc[0], sc[1]);
        m = fmaxf(m, 0.0f);
        atomicMin(&g_hardest[jt * TM + c], __float_as_uint(m));
    }
}

// ---------------- kernel 2: per-entry triplet loss, block-reduced + last-block finalize ----------------
__global__ void __launch_bounds__(256) pairloss_kernel(float* out, int out_n) {
    __shared__ float s_ls[8];
    __shared__ int   s_lc[8];
    int n = g_pp_n;
    if (n > PPCAP) n = PPCAP;
    int lane  = threadIdx.x & 31;
    int warpl = threadIdx.x >> 5;

    float ls = 0.0f;
    int   lc = 0;
    for (int i = blockIdx.x * blockDim.x + threadIdx.x; i < n;
         i += gridDim.x * blockDim.x) {
        unsigned long long e = g_pp[i];
        int   a  = (int)(e >> 32);
        float dp = __uint_as_float((unsigned)e);
        float hn = __uint_as_float(g_hardest[a]);   // +inf => no negative
        if (hn < dp) {
            ls += fmaxf(dp - hn + MARGIN, 0.0f);
            lc += 1;
        }
    }
    #pragma unroll
    for (int o = 16; o > 0; o >>= 1) {
        ls += __shfl_xor_sync(0xffffffffu, ls, o);
        lc += __shfl_xor_sync(0xffffffffu, lc, o);
    }
    if (lane == 0) { s_ls[warpl] = ls; s_lc[warpl] = lc; }
    __syncthreads();
    if (threadIdx.x == 0) {
        float bls = 0.0f;
        int   blc = 0;
        #pragma unroll
        for (int w = 0; w < 8; ++w) { bls += s_ls[w]; blc += s_lc[w]; }
        if (blc) {
            atomicAdd(&g_total, bls);
            atomicAdd(&g_count, blc);
        }
    }

    // last-block finalization
    __syncthreads();
    __threadfence();
    __shared__ int is_last;
    if (threadIdx.x == 0)
        is_last = (atomicAdd(&g_done, 1) == (int)gridDim.x - 1);
    __syncthreads();
    if (is_last) {
        for (int i = threadIdx.x; i < out_n; i += blockDim.x) {
            if (i == 0) {
                int c = g_count;
                out[0] = g_total / (float)(c > 0 ? c : 1);
            } else if (i == 1) {
                out[1] = (float)g_count;
            } else {
                out[i] = 0.0f;
            }
        }
    }
}

extern "C" void kernel_launch(void* const* d_in, const int* in_sizes, int n_in,
                              void* d_out, int out_size) {
    const float* E   = (const float*)d_in[0];
    const void*  lab = d_in[1];

    cudaFuncSetAttribute(pass1_kernel, cudaFuncAttributeMaxDynamicSharedMemorySize, SMEM_SZ);

    init_kernel<<<NB / 32, 256>>>(E, lab);          // 256 blocks, 4 rows/warp
    pass1_kernel<<<NTRI, 256, SMEM_SZ>>>();
    pairloss_kernel<<<PL_GRID, 256>>>((float*)d_out, out_size);
}